// round 2
// baseline (speedup 1.0000x reference)
#include <cuda_runtime.h>

#define VOCABN 101
#define EMBN   32
#define HIDN   32
#define TT     512
#define NB     4096
#define NGATE  128
#define WPB    4     // warps (sequences) per CTA

typedef unsigned long long ull;

// ---------------- packed f32x2 helpers (Blackwell) ----------------
__device__ __forceinline__ ull pack2(float lo, float hi) {
    ull r;
    asm("mov.b64 %0, {%1, %2};" : "=l"(r) : "f"(lo), "f"(hi));
    return r;
}
__device__ __forceinline__ void unpack2(ull v, float& lo, float& hi) {
    asm("mov.b64 {%0, %1}, %2;" : "=f"(lo), "=f"(hi) : "l"(v));
}
__device__ __forceinline__ void fma2(ull& acc, ull a, ull b) {
    asm("fma.rn.f32x2 %0, %1, %2, %0;" : "+l"(acc) : "l"(a), "l"(b));
}
__device__ __forceinline__ void add2(ull& a, ull b) {
    asm("add.rn.f32x2 %0, %0, %1;" : "+l"(a) : "l"(b));
}

// ---------------- fast transcendentals (MUFU ex2 + rcp, ~2ulp) ----------------
__device__ __forceinline__ float ex2f(float x) {
    float r; asm("ex2.approx.f32 %0, %1;" : "=f"(r) : "f"(x)); return r;
}
__device__ __forceinline__ float rcpf(float x) {
    float r; asm("rcp.approx.f32 %0, %1;" : "=f"(r) : "f"(x)); return r;
}
__device__ __forceinline__ float sigmoidf_fast(float x) {
    // 1 / (1 + exp(-x)) = 1 / (1 + 2^(-x*log2e))
    return rcpf(1.0f + ex2f(-1.4426950408889634f * x));
}
__device__ __forceinline__ float tanhf_fast(float x) {
    // tanh(x) = 2*sigmoid(2x) - 1
    float s = rcpf(1.0f + ex2f(-2.8853900817779268f * x));
    return fmaf(2.0f, s, -1.0f);
}

// ---------------- precomputed scratch (device globals: no allocation) ----------------
// gate pre-activation table: table[v] = emb[v] @ Wx + b, stored as packed pairs
//   tabIF[v][l] = (g[l],    g[l+32])   -> (i, f) pair for lane l
//   tabGO[v][l] = (g[l+64], g[l+96])   -> (g, o) pair for lane l
__device__ ull g_tabIF[VOCABN][32];
__device__ ull g_tabGO[VOCABN][32];
// Wh in the same paired layout: WhIF[j][l] = (Wh[j][l], Wh[j][l+32]), etc.
__device__ ull g_WhIF[32][32];
__device__ ull g_WhGO[32][32];

// ---------------- prep kernel: build table + repack Wh ----------------
__global__ void prep_kernel(const float* __restrict__ emb,
                            const float* __restrict__ Wx,
                            const float* __restrict__ Wh,
                            const float* __restrict__ bias) {
    int l = threadIdx.x;   // 0..31
    int v = blockIdx.x;    // 0..VOCABN-1
    if (v < VOCABN) {
        float a0 = 0.f, a1 = 0.f, a2 = 0.f, a3 = 0.f;
#pragma unroll
        for (int e = 0; e < EMBN; e++) {
            float xe = emb[v * EMBN + e];
            const float* w = Wx + e * NGATE;
            a0 = fmaf(xe, w[l],      a0);
            a1 = fmaf(xe, w[l + 32], a1);
            a2 = fmaf(xe, w[l + 64], a2);
            a3 = fmaf(xe, w[l + 96], a3);
        }
        a0 += bias[l];      a1 += bias[l + 32];
        a2 += bias[l + 64]; a3 += bias[l + 96];
        g_tabIF[v][l] = pack2(a0, a1);
        g_tabGO[v][l] = pack2(a2, a3);
    }
    if (v < 32) {
        int j = v;
        g_WhIF[j][l] = pack2(Wh[j * NGATE + l],      Wh[j * NGATE + l + 32]);
        g_WhGO[j][l] = pack2(Wh[j * NGATE + l + 64], Wh[j * NGATE + l + 96]);
    }
}

// ---------------- main LSTM kernel: one warp per sequence ----------------
__global__ void __launch_bounds__(WPB * 32)
lstm_kernel(const int* __restrict__ x,
            const float* __restrict__ W_fc,
            const float* __restrict__ b_fc,
            float* __restrict__ out) {
    // per-warp h staged as duplicated pairs (h_j, h_j) so LDS.128 delivers
    // two FMA-ready packed operands per load
    __shared__ __align__(16) ull hdup[WPB][HIDN];

    const int warp = threadIdx.x >> 5;
    const int lane = threadIdx.x & 31;
    const int b    = blockIdx.x * WPB + warp;

    // Wh register-resident in paired layout (reused 512 times)
    ull wIF[32], wGO[32];
#pragma unroll
    for (int j = 0; j < 32; j++) {
        wIF[j] = g_WhIF[j][lane];
        wGO[j] = g_WhGO[j][lane];
    }

    ull* hrow = hdup[warp];
    hrow[lane] = 0ull;          // (0.0f, 0.0f)
    float c = 0.f;
    float h = 0.f;
    __syncwarp();

    const int* xb = x + b * TT;

    for (int tb = 0; tb < TT; tb += 32) {
        int xv = xb[tb + lane];       // coalesced: 32 timesteps staged per lane
#pragma unroll 8
        for (int s = 0; s < 32; s++) {
            int v = __shfl_sync(0xffffffffu, xv, s);

            // accumulators seeded from precomputed input-gate table
            ull aIF0 = g_tabIF[v][lane];
            ull aGO0 = g_tabGO[v][lane];
            ull aIF1 = 0ull, aGO1 = 0ull;   // second chains for ILP

            const ulonglong2* h2 = (const ulonglong2*)hrow;
#pragma unroll
            for (int k = 0; k < 16; k++) {
                ulonglong2 hv = h2[k];       // broadcast LDS.128: (h_2k,h_2k),(h_2k+1,h_2k+1)
                fma2(aIF0, hv.x, wIF[2 * k]);
                fma2(aGO0, hv.x, wGO[2 * k]);
                fma2(aIF1, hv.y, wIF[2 * k + 1]);
                fma2(aGO1, hv.y, wGO[2 * k + 1]);
            }
            add2(aIF0, aIF1);
            add2(aGO0, aGO1);

            float zi, zf, zg, zo;
            unpack2(aIF0, zi, zf);
            unpack2(aGO0, zg, zo);

            float is = sigmoidf_fast(zi);
            float fs = sigmoidf_fast(zf);
            float gt = tanhf_fast(zg);
            float os = sigmoidf_fast(zo);

            c = fmaf(fs, c, is * gt);
            h = os * tanhf_fast(c);

            __syncwarp();                 // all reads of old h done
            hrow[lane] = pack2(h, h);
            __syncwarp();                 // new h visible before next step's reads
        }
    }

    // final FC: out[b] = h @ W_fc + b_fc   (W_fc is [32,2] row-major)
    float p0 = h * W_fc[2 * lane];
    float p1 = h * W_fc[2 * lane + 1];
#pragma unroll
    for (int off = 16; off; off >>= 1) {
        p0 += __shfl_xor_sync(0xffffffffu, p0, off);
        p1 += __shfl_xor_sync(0xffffffffu, p1, off);
    }
    if (lane == 0) {
        out[2 * b]     = p0 + b_fc[0];
        out[2 * b + 1] = p1 + b_fc[1];
    }
}

extern "C" void kernel_launch(void* const* d_in, const int* in_sizes, int n_in,
                              void* d_out, int out_size) {
    const int*   x    = (const int*)  d_in[0];
    const float* emb  = (const float*)d_in[1];
    const float* Wx   = (const float*)d_in[2];
    const float* Wh   = (const float*)d_in[3];
    const float* bias = (const float*)d_in[4];
    const float* W_fc = (const float*)d_in[5];
    const float* b_fc = (const float*)d_in[6];
    float* out = (float*)d_out;

    prep_kernel<<<VOCABN, 32>>>(emb, Wx, Wh, bias);
    lstm_kernel<<<NB / WPB, WPB * 32>>>(x, W_fc, b_fc, out);
}